// round 15
// baseline (speedup 1.0000x reference)
#include <cuda_runtime.h>
#include <cuda_fp16.h>
#include <cstdint>
#include <math.h>

// ---------------- problem constants ----------------
#define Bn    2
#define Sn    2048
#define HIDn  2048
#define Hn    16
#define Dn    128
#define RANKn 512
#define BSn   (Bn*Sn)        // 4096
#define KVAN  (RANKn+Dn)     // 640
#define HDn   (Hn*Dn)        // 2048

#define MSCALE_F    1.2772588722239781f
#define ATTN_SCALE  0.08838834764831845f

// ---------------- scratch (half everywhere) ----------------
__device__ __half g_hid_h[(size_t)BSn*HIDn];
__device__ __half g_wq_t[(size_t)HDn*HIDn];        // [N=2048][K=2048]
__device__ __half g_wkva_t[(size_t)KVAN*HIDn];     // [640][2048]
__device__ __half g_wkvb_t[(size_t)Hn*2*Dn*RANKn]; // [4096][512]
__device__ __half g_wo_t[(size_t)HIDn*HDn];        // [2048][2048]
__device__ __half g_q_h[(size_t)BSn*HDn];
__device__ __half g_kva_h[(size_t)BSn*KVAN];
__device__ __half g_ckv_h[(size_t)BSn*RANKn];
__device__ __half g_kv_h[(size_t)BSn*Hn*2*Dn];
__device__ __half g_krope_h[(size_t)BSn*Dn];
__device__ __half g_attn_h[(size_t)BSn*HDn];
__device__ float  g_invfreq[Dn/2];

// ---------------- helpers ----------------
__device__ __forceinline__ unsigned h2u(float a, float b) {
    __half2 h = __floats2half2_rn(a, b);
    return *(unsigned*)&h;
}
__device__ __forceinline__ unsigned hadd2u(unsigned a, unsigned b) {
    __half2 r = __hadd2(*(__half2*)&a, *(__half2*)&b);
    return *(unsigned*)&r;
}

__device__ __forceinline__ void mma_f16(float* c, unsigned a0, unsigned a1, unsigned a2,
                                        unsigned a3, unsigned b0, unsigned b1) {
    asm volatile(
        "mma.sync.aligned.m16n8k16.row.col.f32.f16.f16.f32 "
        "{%0,%1,%2,%3}, {%4,%5,%6,%7}, {%8,%9}, {%0,%1,%2,%3};"
        : "+f"(c[0]), "+f"(c[1]), "+f"(c[2]), "+f"(c[3])
        : "r"(a0), "r"(a1), "r"(a2), "r"(a3), "r"(b0), "r"(b1));
}

__device__ __forceinline__ void ldsm4(unsigned& r0, unsigned& r1, unsigned& r2, unsigned& r3,
                                      const __half* p) {
    unsigned a = (unsigned)__cvta_generic_to_shared(p);
    asm volatile("ldmatrix.sync.aligned.m8n8.x4.shared.b16 {%0,%1,%2,%3}, [%4];"
        : "=r"(r0), "=r"(r1), "=r"(r2), "=r"(r3) : "r"(a));
}
__device__ __forceinline__ void ldsm4t(unsigned& r0, unsigned& r1, unsigned& r2, unsigned& r3,
                                       const __half* p) {
    unsigned a = (unsigned)__cvta_generic_to_shared(p);
    asm volatile("ldmatrix.sync.aligned.m8n8.x4.trans.shared.b16 {%0,%1,%2,%3}, [%4];"
        : "=r"(r0), "=r"(r1), "=r"(r2), "=r"(r3) : "r"(a));
}

__device__ __forceinline__ void cp16(void* smem_dst, const void* gmem_src) {
    unsigned d = (unsigned)__cvta_generic_to_shared(smem_dst);
    asm volatile("cp.async.cg.shared.global [%0], [%1], 16;" :: "r"(d), "l"(gmem_src));
}
__device__ __forceinline__ void cp_commit() { asm volatile("cp.async.commit_group;"); }
__device__ __forceinline__ void cp_wait0()  { asm volatile("cp.async.wait_group 0;"); }
__device__ __forceinline__ void cp_wait1()  { asm volatile("cp.async.wait_group 1;"); }

// ---------------- f32 -> half copy (hidden) ----------------
__global__ __launch_bounds__(256) void round_half_kernel(const float* __restrict__ src,
                                                         __half* __restrict__ dst, int n4) {
    int i = blockIdx.x * 256 + threadIdx.x;
    if (i >= n4) return;
    float4 v = ((const float4*)src)[i];
    uint2 o;
    o.x = h2u(v.x, v.y);
    o.y = h2u(v.z, v.w);
    ((uint2*)dst)[i] = o;
}

// ---------------- transpose + halve weights ----------------
__global__ __launch_bounds__(256) void transpose_half_kernel(const float* __restrict__ src,
                                                             __half* __restrict__ dst,
                                                             int K, int N) {
    __shared__ float tile[32][33];
    int k0 = blockIdx.y * 32, n0 = blockIdx.x * 32;
    int tx = threadIdx.x & 31, ty = threadIdx.x >> 5;
    #pragma unroll
    for (int j = 0; j < 32; j += 8)
        tile[ty + j][tx] = src[(size_t)(k0 + ty + j) * N + n0 + tx];
    __syncthreads();
    #pragma unroll
    for (int j = 0; j < 32; j += 8)
        dst[(size_t)(n0 + ty + j) * K + k0 + tx] = __float2half_rn(tile[tx][ty + j]);
}

// ---------------- YaRN inv_freq ----------------
__global__ void init_invfreq_kernel() {
    int i = threadIdx.x;
    if (i >= Dn/2) return;
    const double base = 500000.0;
    const double two_pi = 6.283185307179586;
    double pf = exp(((double)(2*i) / (double)Dn) * log(base));
    double extrap = 1.0 / pf;
    double interp = 1.0 / (16.0 * pf);
    double lowf  = floor((double)Dn * log(8192.0 / (32.0 * two_pi)) / (2.0 * log(base)));
    double highf = ceil ((double)Dn * log(8192.0 / ( 1.0 * two_pi)) / (2.0 * log(base)));
    if (lowf < 0.0) lowf = 0.0;
    if (highf > (double)(Dn-1)) highf = (double)(Dn-1);
    double denom = highf - lowf;
    if (denom < 1.0) denom = 1.0;
    double sm = ((double)i - lowf) / denom;
    sm = fmin(fmax(sm, 0.0), 1.0);
    g_invfreq[i] = (float)((1.0 - sm) * interp + sm * extrap);
}

// ---------------- fp16 GEMM: C[M,N] = A[M,K] @ Bt[N,K]^T ----------------
// BM=128, BN=128, BK=64, 128 threads = 4 warps (2x2), warp tile 64x64.
// 3-stage cp.async ring, wait_group 1, one barrier per K-iteration.
// 8 ldmatrix.x4 -> 32 independent MMAs per k16 step (dense HMMA stream).
#define GSTR 72
#define NSTG 3
#define G_STAGE (128*GSTR)
#define GEMM_SMEM_BYTES (2*NSTG*G_STAGE*2)

__global__ __launch_bounds__(128, 2) void gemm_f16(const __half* __restrict__ A,
                                                   const __half* __restrict__ Bt,
                                                   void* __restrict__ Cv,
                                                   int M, int N, int K, int outHalf) {
    extern __shared__ __half smh[];

    int tid = threadIdx.x;
    int lane = tid & 31, warp = tid >> 5;
    int wm = warp >> 1, wn = warp & 1;           // 2x2 warp grid, 64x64 each
    int bx = blockIdx.x, by = blockIdx.y;

    const int ar  = tid >> 3;                    // 0..15: 8 passes of 16 rows
    const int ac8 = (tid & 7) << 3;

    const __half* Abase = A  + (size_t)(by*128)*K;
    const __half* Bbase = Bt + (size_t)(bx*128)*K;

    float acc[4][8][4];                          // [m16-tile][n8-tile][frag]
    #pragma unroll
    for (int i = 0; i < 4; i++)
        #pragma unroll
        for (int j = 0; j < 8; j++)
            #pragma unroll
            for (int r = 0; r < 4; r++) acc[i][j][r] = 0.f;

    int T = K >> 6;

    auto issue_tile = [&](int t) {
        int s = t % NSTG;
        __half* Ad = smh + s*G_STAGE;
        __half* Bd = smh + (NSTG + s)*G_STAGE;
        int kt = t << 6;
        #pragma unroll
        for (int l = 0; l < 8; l++) {
            int row = ar + l*16;
            cp16(&Ad[row*GSTR + ac8], &Abase[(size_t)row*K + kt + ac8]);
            cp16(&Bd[row*GSTR + ac8], &Bbase[(size_t)row*K + kt + ac8]);
        }
    };

    issue_tile(0);
    cp_commit();
    if (T > 1) issue_tile(1);
    cp_commit();

    const int lm = lane >> 3;
    const int lr = lane & 7;

    for (int t = 0; t < T; t++) {
        cp_wait1();
        __syncthreads();

        if (t + 2 < T) issue_tile(t + 2);
        cp_commit();

        const __half* As_ = smh + (t % NSTG)*G_STAGE;
        const __half* Bs_ = smh + (NSTG + t % NSTG)*G_STAGE;

        #pragma unroll
        for (int ks = 0; ks < 4; ks++) {
            int k0 = ks*16;
            unsigned af[4][4];
            #pragma unroll
            for (int mt = 0; mt < 4; mt++) {
                int row = wm*64 + mt*16 + (lm & 1)*8 + lr;
                int col = k0 + (lm >> 1)*8;
                ldsm4(af[mt][0], af[mt][1], af[mt][2], af[mt][3], &As_[row*GSTR + col]);
            }
            #pragma unroll
            for (int ntp = 0; ntp < 4; ntp++) {
                int nrow = wn*64 + ntp*16 + (lm >> 1)*8 + lr;
                int col  = k0 + (lm & 1)*8;
                unsigned b0, b1, b2, b3;
                ldsm4(b0, b1, b2, b3, &Bs_[nrow*GSTR + col]);
                #pragma unroll
                for (int mt = 0; mt < 4; mt++) {
                    mma_f16(acc[mt][ntp*2],   af[mt][0], af[mt][1], af[mt][2], af[mt][3], b0, b1);
                    mma_f16(acc[mt][ntp*2+1], af[mt][0], af[mt][1], af[mt][2], af[mt][3], b2, b3);
                }
            }
        }
    }

    if (outHalf) {
        __half* C = (__half*)Cv;
        #pragma unroll
        for (int mt = 0; mt < 4; mt++) {
            int row = by*128 + wm*64 + mt*16 + (lane >> 2);
            #pragma unroll
            for (int nt = 0; nt < 8; nt++) {
                int col = bx*128 + wn*64 + nt*8 + 2*(lane & 3);
                *(unsigned*)&C[(size_t)row*N + col]     = h2u(acc[mt][nt][0], acc[mt][nt][1]);
                *(unsigned*)&C[(size_t)(row+8)*N + col] = h2u(acc[mt][nt][2], acc[mt][nt][3]);
            }
        }
    } else {
        float* C = (float*)Cv;
        #pragma unroll
        for (int mt = 0; mt < 4; mt++) {
            int row = by*128 + wm*64 + mt*16 + (lane >> 2);
            #pragma unroll
            for (int nt = 0; nt < 8; nt++) {
                int col = bx*128 + wn*64 + nt*8 + 2*(lane & 3);
                *(float2*)&C[(size_t)row*N + col]     = make_float2(acc[mt][nt][0], acc[mt][nt][1]);
                *(float2*)&C[(size_t)(row+8)*N + col] = make_float2(acc[mt][nt][2], acc[mt][nt][3]);
            }
        }
    }
}

// ---------------- RMSNorm ----------------
__global__ __launch_bounds__(128) void rmsnorm_kernel(const float* __restrict__ w) {
    int row = blockIdx.x;
    const __half* x = g_kva_h + (size_t)row * KVAN;
    __half* y = g_ckv_h + (size_t)row * RANKn;
    int tid = threadIdx.x;
    uint2 u = *(const uint2*)&x[tid*4];
    __half2 h0 = *(__half2*)&u.x, h1 = *(__half2*)&u.y;
    float f0 = __low2float(h0), f1 = __high2float(h0);
    float f2 = __low2float(h1), f3 = __high2float(h1);
    float ss = f0*f0 + f1*f1 + f2*f2 + f3*f3;
    #pragma unroll
    for (int off = 16; off >= 1; off >>= 1)
        ss += __shfl_xor_sync(0xffffffffu, ss, off);
    __shared__ float warp_s[4];
    if ((tid & 31) == 0) warp_s[tid >> 5] = ss;
    __syncthreads();
    float total = warp_s[0] + warp_s[1] + warp_s[2] + warp_s[3];
    float inv = rsqrtf(total * (1.0f/(float)RANKn) + 1e-6f);
    float4 wv = *(const float4*)&w[tid*4];
    uint2 o;
    o.x = h2u(f0*wv.x*inv, f1*wv.y*inv);
    o.y = h2u(f2*wv.z*inv, f3*wv.w*inv);
    *(uint2*)&y[tid*4] = o;
}

// ---------------- RoPE q ----------------
__global__ __launch_bounds__(256) void rope_q_kernel(const int* __restrict__ pos_ids) {
    int t = blockIdx.x * 4 + (threadIdx.x >> 6);
    int d = threadIdx.x & 63;
    int bs = t >> 4;
    float p = (float)pos_ids[bs];
    float f = p * g_invfreq[d];
    float sv, cv;
    sincosf(f, &sv, &cv);
    cv *= MSCALE_F; sv *= MSCALE_F;
    __half* q = g_q_h + (size_t)t * Dn;
    float x0 = __half2float(q[d]), x1 = __half2float(q[d+64]);
    q[d]    = __float2half_rn((x0*cv - x1*sv) * ATTN_SCALE);
    q[d+64] = __float2half_rn((x1*cv + x0*sv) * ATTN_SCALE);
}

// ---------------- RoPE k_rope ----------------
__global__ __launch_bounds__(256) void rope_k_kernel(const int* __restrict__ pos_ids) {
    int bs = blockIdx.x * 4 + (threadIdx.x >> 6);
    int d = threadIdx.x & 63;
    float p = (float)pos_ids[bs];
    float f = p * g_invfreq[d];
    float sv, cv;
    sincosf(f, &sv, &cv);
    cv *= MSCALE_F; sv *= MSCALE_F;
    const __half* kr = g_kva_h + (size_t)bs * KVAN + RANKn;
    float x0 = __half2float(kr[d]), x1 = __half2float(kr[d+64]);
    __half* o = g_krope_h + (size_t)bs * Dn;
    o[d]    = __float2half_rn(x0*cv - x1*sv);
    o[d+64] = __float2half_rn(x1*cv + x0*sv);
}

// ---------------- fp16 flash attention (unchanged from 602.5us best) ----------------
#define KSTR 136
#define FSTG (64*KSTR)
#define FLASH_SMEM_BYTES (4*FSTG*2)

__global__ __launch_bounds__(256) void flash_f16_kernel() {
    extern __shared__ __half smh[];

    int tid = threadIdx.x;
    int lane = tid & 31, w = tid >> 5;
    int qt = gridDim.x - 1 - blockIdx.x;
    int bh = blockIdx.y;
    int b = bh >> 4, h = bh & 15;

    const int lm = lane >> 3, lr = lane & 7;
    const int r0 = w*16 + (lane >> 2);

    __half* Qs = smh + 2*FSTG;
    const __half* qbase = g_q_h + ((size_t)(b*Sn + qt*128)) * HDn + h*Dn;
    #pragma unroll
    for (int t8 = 0; t8 < 8; t8++) {
        int i = tid + t8*256;
        int r = i >> 4, d8 = (i & 15) << 3;
        *(uint4*)&Qs[r*KSTR + d8] = *(const uint4*)&qbase[(size_t)r*HDn + d8];
    }
    __syncthreads();
    unsigned qf[8][4];
    #pragma unroll
    for (int ks = 0; ks < 8; ks++) {
        int row = w*16 + (lm & 1)*8 + lr;
        int col = ks*16 + (lm >> 1)*8;
        ldsm4(qf[ks][0], qf[ks][1], qf[ks][2], qf[ks][3], &Qs[row*KSTR + col]);
    }
    __syncthreads();

    float o[16][4];
    float m0 = -1e30f, m1 = -1e30f, l0 = 0.f, l1 = 0.f;
    #pragma unroll
    for (int nt = 0; nt < 16; nt++)
        #pragma unroll
        for (int r = 0; r < 4; r++) o[nt][r] = 0.f;

    const int nkt = 2*qt + 2;
    uint4 kn[4], kr4[4];

    {
        size_t tok0 = (size_t)(b*Sn);
        __half* Vs = smh + FSTG;
        #pragma unroll
        for (int c = 0; c < 4; c++) {
            int i = tid + c*256;
            int r = i >> 4, d8 = (i & 15) << 3;
            size_t base = (tok0 + r)*((size_t)Hn*2*Dn) + h*256;
            kn[c]  = *(const uint4*)&g_kv_h[base + d8];
            kr4[c] = *(const uint4*)&g_krope_h[(tok0 + r)*Dn + d8];
            cp16(&Vs[r*KSTR + d8], &g_kv_h[base + 128 + d8]);
        }
        cp_commit();
    }

    for (int kt = 0; kt < nkt; kt++) {
        int st = kt & 1;
        __half* Ks = smh + st*2*FSTG;
        __half* Vs = Ks + FSTG;

        #pragma unroll
        for (int c = 0; c < 4; c++) {
            int i = tid + c*256;
            int r = i >> 4, d8 = (i & 15) << 3;
            uint4 ko;
            ko.x = hadd2u(kn[c].x, kr4[c].x);
            ko.y = hadd2u(kn[c].y, kr4[c].y);
            ko.z = hadd2u(kn[c].z, kr4[c].z);
            ko.w = hadd2u(kn[c].w, kr4[c].w);
            *(uint4*)&Ks[r*KSTR + d8] = ko;
        }
        cp_wait0();
        __syncthreads();

        if (kt + 1 < nkt) {
            size_t tok1 = (size_t)(b*Sn + (kt+1)*64);
            __half* Vn = smh + (st ^ 1)*2*FSTG + FSTG;
            #pragma unroll
            for (int c = 0; c < 4; c++) {
                int i = tid + c*256;
                int r = i >> 4, d8 = (i & 15) << 3;
                size_t base = (tok1 + r)*((size_t)Hn*2*Dn) + h*256;
                kn[c]  = *(const uint4*)&g_kv_h[base + d8];
                kr4[c] = *(const uint4*)&g_krope_h[(tok1 + r)*Dn + d8];
                cp16(&Vn[r*KSTR + d8], &g_kv_h[base + 128 + d8]);
            }
            cp_commit();
        }

        float sacc[8][4];
        #pragma unroll
        for (int nt = 0; nt < 8; nt++)
            #pragma unroll
            for (int r = 0; r < 4; r++) sacc[nt][r] = 0.f;

        #pragma unroll
        for (int ks = 0; ks < 8; ks++) {
            int k0 = ks*16;
            #pragma unroll
            for (int nt = 0; nt < 8; nt++) {
                int n = nt*8 + (lane >> 2);
                unsigned b0 = *(const unsigned*)&Ks[n*KSTR + k0 + 2*(lane & 3)];
                unsigned b1 = *(const unsigned*)&Ks[n*KSTR + k0 + 2*(lane & 3) + 8];
                mma_f16(sacc[nt], qf[ks][0], qf[ks][1], qf[ks][2], qf[ks][3], b0, b1);
            }
        }

        if (kt*64 + 63 > qt*128 + w*16) {
            int qg0 = qt*128 + r0, qg1 = qg0 + 8;
            #pragma unroll
            for (int nt = 0; nt < 8; nt++) {
                int c = kt*64 + nt*8 + 2*(lane & 3);
                if (c     > qg0) sacc[nt][0] = -1e30f;
                if (c + 1 > qg0) sacc[nt][1] = -1e30f;
                if (c     > qg1) sacc[nt][2] = -1e30f;
                if (c + 1 > qg1) sacc[nt][3] = -1e30f;
            }
        }

        float mx0 = -1e30f, mx1 = -1e30f;
        #pragma unroll
        for (int nt = 0; nt < 8; nt++) {
            mx0 = fmaxf(mx0, fmaxf(sacc[nt][0], sacc[nt][1]));
            mx1 = fmaxf(mx1, fmaxf(sacc[nt][2], sacc[nt][3]));
        }
        mx0 = fmaxf(mx0, __shfl_xor_sync(0xffffffffu, mx0, 1));
        mx0 = fmaxf(mx0, __shfl_xor_sync(0xffffffffu, mx0, 2));
        mx1 = fmaxf(mx1, __shfl_xor_sync(0xffffffffu, mx1, 1));
        mx1 = fmaxf(mx1, __shfl_xor_sync(0xffffffffu, mx1, 2));
        float mn0 = fmaxf(m0, mx0), mn1 = fmaxf(m1, mx1);
        float corr0 = __expf(m0 - mn0), corr1 = __expf(m1 - mn1);
        m0 = mn0; m1 = mn1;

        float sum0 = 0.f, sum1 = 0.f;
        #pragma unroll
        for (int nt = 0; nt < 8; nt++) {
            sacc[nt][0] = __expf(sacc[nt][0] - mn0);
            sacc[nt][1] = __expf(sacc[nt][1] - mn0);
            sacc[nt][2] = __expf(sacc[nt][2] - mn1);
            sacc[nt][3] = __expf(sacc[nt][3] - mn1);
            sum0 += sacc[nt][0] + sacc[nt][1];
            sum1 += sacc[nt][2] + sacc[nt][3];
        }
        sum0 += __shfl_xor_sync(0xffffffffu, sum0, 1);
        sum0 += __shfl_xor_sync(0xffffffffu, sum0, 2);
        sum1 += __shfl_xor_sync(0xffffffffu, sum1, 1);
        sum1 += __shfl_xor_sync(0xffffffffu, sum1, 2);
        l0 = l0*corr0 + sum0;
        l1 = l1*corr1 + sum1;

        #pragma unroll
        for (int nt = 0; nt < 16; nt++) {
            o[nt][0] *= corr0; o[nt][1] *= corr0;
            o[nt][2] *= corr1; o[nt][3] *= corr1;
        }

        #pragma unroll
        for (int kc = 0; kc < 4; kc++) {
            unsigned pa0 = h2u(sacc[2*kc][0],   sacc[2*kc][1]);
            unsigned pa1 = h2u(sacc[2*kc][2],   sacc[2*kc][3]);
            unsigned pa2 = h2u(sacc[2*kc+1][0], sacc[2*kc+1][1]);
            unsigned pa3 = h2u(sacc[2*kc+1][2], sacc[2*kc+1][3]);
            int k0 = kc*16;
            #pragma unroll
            for (int dt = 0; dt < 8; dt++) {
                int vrow = k0 + (lm & 1)*8 + lr;
                int vcol = dt*16 + (lm >> 1)*8;
                unsigned b0, b1, b2, b3;
                ldsm4t(b0, b1, b2, b3, &Vs[vrow*KSTR + vcol]);
                mma_f16(o[2*dt],   pa0, pa1, pa2, pa3, b0, b1);
                mma_f16(o[2*dt+1], pa0, pa1, pa2, pa3, b2, b3);
            }
        }
    }

    float inv0 = 1.0f / (l0 + 1e-5f);
    float inv1 = 1.0f / (l1 + 1e-5f);
    size_t row0 = (size_t)(b*Sn + qt*128 + r0);
    __half* op0 = g_attn_h + row0*HDn + h*Dn;
    __half* op1 = g_attn_h + (row0+8)*HDn + h*Dn;
    #pragma unroll
    for (int nt = 0; nt < 16; nt++) {
        int d = nt*8 + 2*(lane & 3);
        *(unsigned*)&op0[d] = h2u(o[nt][0]*inv0, o[nt][1]*inv0);
        *(unsigned*)&op1[d] = h2u(o[nt][2]*inv1, o[nt][3]*inv1);
    }
}

// ---------------- launch ----------------
extern "C" void kernel_launch(void* const* d_in, const int* in_sizes, int n_in,
                              void* d_out, int out_size) {
    const float* hidden  = (const float*)d_in[0];
    const int*   pos_ids = (const int*)  d_in[1];
    const float* w_q     = (const float*)d_in[2];
    const float* w_kv_a  = (const float*)d_in[3];
    const float* w_kv_b  = (const float*)d_in[4];
    const float* w_o     = (const float*)d_in[5];
    const float* kv_ln_w = (const float*)d_in[6];
    float* out = (float*)d_out;

    __half *phid, *pwq, *pwkva, *pwkvb, *pwo;
    __half *pq, *pkva, *pckv, *pkv, *pattn;
    cudaGetSymbolAddress((void**)&phid,  g_hid_h);
    cudaGetSymbolAddress((void**)&pwq,   g_wq_t);
    cudaGetSymbolAddress((void**)&pwkva, g_wkva_t);
    cudaGetSymbolAddress((void**)&pwkvb, g_wkvb_t);
    cudaGetSymbolAddress((void**)&pwo,   g_wo_t);
    cudaGetSymbolAddress((void**)&pq,    g_q_h);
    cudaGetSymbolAddress((void**)&pkva,  g_kva_h);
    cudaGetSymbolAddress((void**)&pckv,  g_ckv_h);
    cudaGetSymbolAddress((void**)&pkv,   g_kv_h);
    cudaGetSymbolAddress((void**)&pattn, g_attn_h);

    cudaFuncSetAttribute(gemm_f16, cudaFuncAttributeMaxDynamicSharedMemorySize,
                         GEMM_SMEM_BYTES);
    cudaFuncSetAttribute(flash_f16_kernel, cudaFuncAttributeMaxDynamicSharedMemorySize,
                         FLASH_SMEM_BYTES);

    init_invfreq_kernel<<<1, 64>>>();
    round_half_kernel<<<(BSn*HIDn/4 + 255)/256, 256>>>(hidden, phid, BSn*HIDn/4);

    transpose_half_kernel<<<dim3(HDn/32, HIDn/32), 256>>>(w_q, pwq, HIDn, HDn);
    gemm_f16<<<dim3(HDn/128, BSn/128), 128, GEMM_SMEM_BYTES>>>(phid, pwq, pq, BSn, HDn, HIDn, 1);

    transpose_half_kernel<<<dim3(KVAN/32, HIDn/32), 256>>>(w_kv_a, pwkva, HIDn, KVAN);
    gemm_f16<<<dim3(KVAN/128, BSn/128), 128, GEMM_SMEM_BYTES>>>(phid, pwkva, pkva, BSn, KVAN, HIDn, 1);

    rmsnorm_kernel<<<BSn, 128>>>(kv_ln_w);
    rope_k_kernel<<<BSn/4, 256>>>(pos_ids);

    transpose_half_kernel<<<dim3((Hn*2*Dn)/32, RANKn/32), 256>>>(w_kv_b, pwkvb, RANKn, Hn*2*Dn);
    gemm_f16<<<dim3((Hn*2*Dn)/128, BSn/128), 128, GEMM_SMEM_BYTES>>>(pckv, pwkvb, pkv, BSn, Hn*2*Dn, RANKn, 1);

    rope_q_kernel<<<(BSn*Hn)/4, 256>>>(pos_ids);

    flash_f16_kernel<<<dim3(Sn/128, Bn*Hn), 256, FLASH_SMEM_BYTES>>>();

    transpose_half_kernel<<<dim3(HIDn/32, HDn/32), 256>>>(w_o, pwo, HDn, HIDn);
    gemm_f16<<<dim3(HIDn/128, BSn/128), 128, GEMM_SMEM_BYTES>>>(pattn, pwo, out, BSn, HIDn, HIDn, 0);
}

// round 16
// speedup vs baseline: 1.0128x; 1.0128x over previous
#include <cuda_runtime.h>
#include <cuda_fp16.h>
#include <cstdint>
#include <math.h>

// ---------------- problem constants ----------------
#define Bn    2
#define Sn    2048
#define HIDn  2048
#define Hn    16
#define Dn    128
#define RANKn 512
#define BSn   (Bn*Sn)        // 4096
#define KVAN  (RANKn+Dn)     // 640
#define HDn   (Hn*Dn)        // 2048

#define MSCALE_F    1.2772588722239781f
#define ATTN_SCALE  0.08838834764831845f

// ---------------- scratch (half everywhere) ----------------
__device__ __half g_hid_h[(size_t)BSn*HIDn];
__device__ __half g_wq_t[(size_t)HDn*HIDn];        // [N=2048][K=2048]
__device__ __half g_wkva_t[(size_t)KVAN*HIDn];     // [640][2048]
__device__ __half g_wkvb_t[(size_t)Hn*2*Dn*RANKn]; // [4096][512]
__device__ __half g_wo_t[(size_t)HIDn*HDn];        // [2048][2048]
__device__ __half g_q_h[(size_t)BSn*HDn];
__device__ __half g_kva_h[(size_t)BSn*KVAN];
__device__ __half g_ckv_h[(size_t)BSn*RANKn];
__device__ __half g_kv_h[(size_t)BSn*Hn*2*Dn];
__device__ __half g_krope_h[(size_t)BSn*Dn];
__device__ __half g_attn_h[(size_t)BSn*HDn];
__device__ float  g_invfreq[Dn/2];

// ---------------- helpers ----------------
__device__ __forceinline__ unsigned h2u(float a, float b) {
    __half2 h = __floats2half2_rn(a, b);
    return *(unsigned*)&h;
}
__device__ __forceinline__ unsigned hadd2u(unsigned a, unsigned b) {
    __half2 r = __hadd2(*(__half2*)&a, *(__half2*)&b);
    return *(unsigned*)&r;
}

__device__ __forceinline__ void mma_f16(float* c, unsigned a0, unsigned a1, unsigned a2,
                                        unsigned a3, unsigned b0, unsigned b1) {
    asm volatile(
        "mma.sync.aligned.m16n8k16.row.col.f32.f16.f16.f32 "
        "{%0,%1,%2,%3}, {%4,%5,%6,%7}, {%8,%9}, {%0,%1,%2,%3};"
        : "+f"(c[0]), "+f"(c[1]), "+f"(c[2]), "+f"(c[3])
        : "r"(a0), "r"(a1), "r"(a2), "r"(a3), "r"(b0), "r"(b1));
}

__device__ __forceinline__ void ldsm4(unsigned& r0, unsigned& r1, unsigned& r2, unsigned& r3,
                                      const __half* p) {
    unsigned a = (unsigned)__cvta_generic_to_shared(p);
    asm volatile("ldmatrix.sync.aligned.m8n8.x4.shared.b16 {%0,%1,%2,%3}, [%4];"
        : "=r"(r0), "=r"(r1), "=r"(r2), "=r"(r3) : "r"(a));
}
__device__ __forceinline__ void ldsm4t(unsigned& r0, unsigned& r1, unsigned& r2, unsigned& r3,
                                       const __half* p) {
    unsigned a = (unsigned)__cvta_generic_to_shared(p);
    asm volatile("ldmatrix.sync.aligned.m8n8.x4.trans.shared.b16 {%0,%1,%2,%3}, [%4];"
        : "=r"(r0), "=r"(r1), "=r"(r2), "=r"(r3) : "r"(a));
}

__device__ __forceinline__ void cp16(void* smem_dst, const void* gmem_src) {
    unsigned d = (unsigned)__cvta_generic_to_shared(smem_dst);
    asm volatile("cp.async.cg.shared.global [%0], [%1], 16;" :: "r"(d), "l"(gmem_src));
}
__device__ __forceinline__ void cp_commit() { asm volatile("cp.async.commit_group;"); }
__device__ __forceinline__ void cp_wait0()  { asm volatile("cp.async.wait_group 0;"); }
__device__ __forceinline__ void cp_wait1()  { asm volatile("cp.async.wait_group 1;"); }

// ---------------- f32 -> half copy (hidden) ----------------
__global__ __launch_bounds__(256) void round_half_kernel(const float* __restrict__ src,
                                                         __half* __restrict__ dst, int n4) {
    int i = blockIdx.x * 256 + threadIdx.x;
    if (i >= n4) return;
    float4 v = ((const float4*)src)[i];
    uint2 o;
    o.x = h2u(v.x, v.y);
    o.y = h2u(v.z, v.w);
    ((uint2*)dst)[i] = o;
}

// ---------------- transpose + halve weights ----------------
__global__ __launch_bounds__(256) void transpose_half_kernel(const float* __restrict__ src,
                                                             __half* __restrict__ dst,
                                                             int K, int N) {
    __shared__ float tile[32][33];
    int k0 = blockIdx.y * 32, n0 = blockIdx.x * 32;
    int tx = threadIdx.x & 31, ty = threadIdx.x >> 5;
    #pragma unroll
    for (int j = 0; j < 32; j += 8)
        tile[ty + j][tx] = src[(size_t)(k0 + ty + j) * N + n0 + tx];
    __syncthreads();
    #pragma unroll
    for (int j = 0; j < 32; j += 8)
        dst[(size_t)(n0 + ty + j) * K + k0 + tx] = __float2half_rn(tile[tx][ty + j]);
}

// ---------------- YaRN inv_freq ----------------
__global__ void init_invfreq_kernel() {
    int i = threadIdx.x;
    if (i >= Dn/2) return;
    const double base = 500000.0;
    const double two_pi = 6.283185307179586;
    double pf = exp(((double)(2*i) / (double)Dn) * log(base));
    double extrap = 1.0 / pf;
    double interp = 1.0 / (16.0 * pf);
    double lowf  = floor((double)Dn * log(8192.0 / (32.0 * two_pi)) / (2.0 * log(base)));
    double highf = ceil ((double)Dn * log(8192.0 / ( 1.0 * two_pi)) / (2.0 * log(base)));
    if (lowf < 0.0) lowf = 0.0;
    if (highf > (double)(Dn-1)) highf = (double)(Dn-1);
    double denom = highf - lowf;
    if (denom < 1.0) denom = 1.0;
    double sm = ((double)i - lowf) / denom;
    sm = fmin(fmax(sm, 0.0), 1.0);
    g_invfreq[i] = (float)((1.0 - sm) * interp + sm * extrap);
}

// ---------------- fp16 GEMM (R15 config: 4 warps, 64x64 warp tile) ----------------
#define GSTR 72
#define NSTG 3
#define G_STAGE (128*GSTR)
#define GEMM_SMEM_BYTES (2*NSTG*G_STAGE*2)

__global__ __launch_bounds__(128, 2) void gemm_f16(const __half* __restrict__ A,
                                                   const __half* __restrict__ Bt,
                                                   void* __restrict__ Cv,
                                                   int M, int N, int K, int outHalf) {
    extern __shared__ __half smh[];

    int tid = threadIdx.x;
    int lane = tid & 31, warp = tid >> 5;
    int wm = warp >> 1, wn = warp & 1;
    int bx = blockIdx.x, by = blockIdx.y;

    const int ar  = tid >> 3;
    const int ac8 = (tid & 7) << 3;

    const __half* Abase = A  + (size_t)(by*128)*K;
    const __half* Bbase = Bt + (size_t)(bx*128)*K;

    float acc[4][8][4];
    #pragma unroll
    for (int i = 0; i < 4; i++)
        #pragma unroll
        for (int j = 0; j < 8; j++)
            #pragma unroll
            for (int r = 0; r < 4; r++) acc[i][j][r] = 0.f;

    int T = K >> 6;

    auto issue_tile = [&](int t) {
        int s = t % NSTG;
        __half* Ad = smh + s*G_STAGE;
        __half* Bd = smh + (NSTG + s)*G_STAGE;
        int kt = t << 6;
        #pragma unroll
        for (int l = 0; l < 8; l++) {
            int row = ar + l*16;
            cp16(&Ad[row*GSTR + ac8], &Abase[(size_t)row*K + kt + ac8]);
            cp16(&Bd[row*GSTR + ac8], &Bbase[(size_t)row*K + kt + ac8]);
        }
    };

    issue_tile(0);
    cp_commit();
    if (T > 1) issue_tile(1);
    cp_commit();

    const int lm = lane >> 3;
    const int lr = lane & 7;

    for (int t = 0; t < T; t++) {
        cp_wait1();
        __syncthreads();

        if (t + 2 < T) issue_tile(t + 2);
        cp_commit();

        const __half* As_ = smh + (t % NSTG)*G_STAGE;
        const __half* Bs_ = smh + (NSTG + t % NSTG)*G_STAGE;

        #pragma unroll
        for (int ks = 0; ks < 4; ks++) {
            int k0 = ks*16;
            unsigned af[4][4];
            #pragma unroll
            for (int mt = 0; mt < 4; mt++) {
                int row = wm*64 + mt*16 + (lm & 1)*8 + lr;
                int col = k0 + (lm >> 1)*8;
                ldsm4(af[mt][0], af[mt][1], af[mt][2], af[mt][3], &As_[row*GSTR + col]);
            }
            #pragma unroll
            for (int ntp = 0; ntp < 4; ntp++) {
                int nrow = wn*64 + ntp*16 + (lm >> 1)*8 + lr;
                int col  = k0 + (lm & 1)*8;
                unsigned b0, b1, b2, b3;
                ldsm4(b0, b1, b2, b3, &Bs_[nrow*GSTR + col]);
                #pragma unroll
                for (int mt = 0; mt < 4; mt++) {
                    mma_f16(acc[mt][ntp*2],   af[mt][0], af[mt][1], af[mt][2], af[mt][3], b0, b1);
                    mma_f16(acc[mt][ntp*2+1], af[mt][0], af[mt][1], af[mt][2], af[mt][3], b2, b3);
                }
            }
        }
    }

    if (outHalf) {
        __half* C = (__half*)Cv;
        #pragma unroll
        for (int mt = 0; mt < 4; mt++) {
            int row = by*128 + wm*64 + mt*16 + (lane >> 2);
            #pragma unroll
            for (int nt = 0; nt < 8; nt++) {
                int col = bx*128 + wn*64 + nt*8 + 2*(lane & 3);
                *(unsigned*)&C[(size_t)row*N + col]     = h2u(acc[mt][nt][0], acc[mt][nt][1]);
                *(unsigned*)&C[(size_t)(row+8)*N + col] = h2u(acc[mt][nt][2], acc[mt][nt][3]);
            }
        }
    } else {
        float* C = (float*)Cv;
        #pragma unroll
        for (int mt = 0; mt < 4; mt++) {
            int row = by*128 + wm*64 + mt*16 + (lane >> 2);
            #pragma unroll
            for (int nt = 0; nt < 8; nt++) {
                int col = bx*128 + wn*64 + nt*8 + 2*(lane & 3);
                *(float2*)&C[(size_t)row*N + col]     = make_float2(acc[mt][nt][0], acc[mt][nt][1]);
                *(float2*)&C[(size_t)(row+8)*N + col] = make_float2(acc[mt][nt][2], acc[mt][nt][3]);
            }
        }
    }
}

// ---------------- fused RMSNorm + RoPE-k (both read g_kva rows) ----------------
__global__ __launch_bounds__(128) void norm_ropek_kernel(const float* __restrict__ w,
                                                         const int* __restrict__ pos_ids) {
    int row = blockIdx.x;
    const __half* x = g_kva_h + (size_t)row * KVAN;
    __half* y = g_ckv_h + (size_t)row * RANKn;
    int tid = threadIdx.x;
    uint2 u = *(const uint2*)&x[tid*4];
    __half2 h0 = *(__half2*)&u.x, h1 = *(__half2*)&u.y;
    float f0 = __low2float(h0), f1 = __high2float(h0);
    float f2 = __low2float(h1), f3 = __high2float(h1);
    float ss = f0*f0 + f1*f1 + f2*f2 + f3*f3;
    #pragma unroll
    for (int off = 16; off >= 1; off >>= 1)
        ss += __shfl_xor_sync(0xffffffffu, ss, off);
    __shared__ float warp_s[4];
    if ((tid & 31) == 0) warp_s[tid >> 5] = ss;
    __syncthreads();
    float total = warp_s[0] + warp_s[1] + warp_s[2] + warp_s[3];
    float inv = rsqrtf(total * (1.0f/(float)RANKn) + 1e-6f);
    float4 wv = *(const float4*)&w[tid*4];
    uint2 o;
    o.x = h2u(f0*wv.x*inv, f1*wv.y*inv);
    o.y = h2u(f2*wv.z*inv, f3*wv.w*inv);
    *(uint2*)&y[tid*4] = o;

    // rope on the trailing 128 cols (threads 0..63), independent of the norm
    if (tid < 64) {
        float p = (float)pos_ids[row];
        float f = p * g_invfreq[tid];
        float sv, cv;
        sincosf(f, &sv, &cv);
        cv *= MSCALE_F; sv *= MSCALE_F;
        const __half* kr = x + RANKn;
        float x0 = __half2float(kr[tid]), x1 = __half2float(kr[tid+64]);
        __half* ok = g_krope_h + (size_t)row * Dn;
        ok[tid]    = __float2half_rn(x0*cv - x1*sv);
        ok[tid+64] = __float2half_rn(x1*cv + x0*sv);
    }
}

// ---------------- RoPE q ----------------
__global__ __launch_bounds__(256) void rope_q_kernel(const int* __restrict__ pos_ids) {
    int t = blockIdx.x * 4 + (threadIdx.x >> 6);
    int d = threadIdx.x & 63;
    int bs = t >> 4;
    float p = (float)pos_ids[bs];
    float f = p * g_invfreq[d];
    float sv, cv;
    sincosf(f, &sv, &cv);
    cv *= MSCALE_F; sv *= MSCALE_F;
    __half* q = g_q_h + (size_t)t * Dn;
    float x0 = __half2float(q[d]), x1 = __half2float(q[d+64]);
    q[d]    = __float2half_rn((x0*cv - x1*sv) * ATTN_SCALE);
    q[d+64] = __float2half_rn((x1*cv + x0*sv) * ATTN_SCALE);
}

// ---------------- fp16 flash attention: S B-frags via ldmatrix ----------------
#define KSTR 136
#define FSTG (64*KSTR)
#define FLASH_SMEM_BYTES (4*FSTG*2)

__global__ __launch_bounds__(256) void flash_f16_kernel() {
    extern __shared__ __half smh[];

    int tid = threadIdx.x;
    int lane = tid & 31, w = tid >> 5;
    int qt = gridDim.x - 1 - blockIdx.x;
    int bh = blockIdx.y;
    int b = bh >> 4, h = bh & 15;

    const int lm = lane >> 3, lr = lane & 7;
    const int r0 = w*16 + (lane >> 2);

    __half* Qs = smh + 2*FSTG;
    const __half* qbase = g_q_h + ((size_t)(b*Sn + qt*128)) * HDn + h*Dn;
    #pragma unroll
    for (int t8 = 0; t8 < 8; t8++) {
        int i = tid + t8*256;
        int r = i >> 4, d8 = (i & 15) << 3;
        *(uint4*)&Qs[r*KSTR + d8] = *(const uint4*)&qbase[(size_t)r*HDn + d8];
    }
    __syncthreads();
    unsigned qf[8][4];
    #pragma unroll
    for (int ks = 0; ks < 8; ks++) {
        int row = w*16 + (lm & 1)*8 + lr;
        int col = ks*16 + (lm >> 1)*8;
        ldsm4(qf[ks][0], qf[ks][1], qf[ks][2], qf[ks][3], &Qs[row*KSTR + col]);
    }
    __syncthreads();

    float o[16][4];
    float m0 = -1e30f, m1 = -1e30f, l0 = 0.f, l1 = 0.f;
    #pragma unroll
    for (int nt = 0; nt < 16; nt++)
        #pragma unroll
        for (int r = 0; r < 4; r++) o[nt][r] = 0.f;

    const int nkt = 2*qt + 2;
    uint4 kn[4], kr4[4];

    {
        size_t tok0 = (size_t)(b*Sn);
        __half* Vs = smh + FSTG;
        #pragma unroll
        for (int c = 0; c < 4; c++) {
            int i = tid + c*256;
            int r = i >> 4, d8 = (i & 15) << 3;
            size_t base = (tok0 + r)*((size_t)Hn*2*Dn) + h*256;
            kn[c]  = *(const uint4*)&g_kv_h[base + d8];
            kr4[c] = *(const uint4*)&g_krope_h[(tok0 + r)*Dn + d8];
            cp16(&Vs[r*KSTR + d8], &g_kv_h[base + 128 + d8]);
        }
        cp_commit();
    }

    for (int kt = 0; kt < nkt; kt++) {
        int st = kt & 1;
        __half* Ks = smh + st*2*FSTG;
        __half* Vs = Ks + FSTG;

        #pragma unroll
        for (int c = 0; c < 4; c++) {
            int i = tid + c*256;
            int r = i >> 4, d8 = (i & 15) << 3;
            uint4 ko;
            ko.x = hadd2u(kn[c].x, kr4[c].x);
            ko.y = hadd2u(kn[c].y, kr4[c].y);
            ko.z = hadd2u(kn[c].z, kr4[c].z);
            ko.w = hadd2u(kn[c].w, kr4[c].w);
            *(uint4*)&Ks[r*KSTR + d8] = ko;
        }
        cp_wait0();
        __syncthreads();

        if (kt + 1 < nkt) {
            size_t tok1 = (size_t)(b*Sn + (kt+1)*64);
            __half* Vn = smh + (st ^ 1)*2*FSTG + FSTG;
            #pragma unroll
            for (int c = 0; c < 4; c++) {
                int i = tid + c*256;
                int r = i >> 4, d8 = (i & 15) << 3;
                size_t base = (tok1 + r)*((size_t)Hn*2*Dn) + h*256;
                kn[c]  = *(const uint4*)&g_kv_h[base + d8];
                kr4[c] = *(const uint4*)&g_krope_h[(tok1 + r)*Dn + d8];
                cp16(&Vn[r*KSTR + d8], &g_kv_h[base + 128 + d8]);
            }
            cp_commit();
        }

        // ---- S = Q @ K^T : B-frags via ldmatrix (GEMM-validated pattern) ----
        float sacc[8][4];
        #pragma unroll
        for (int nt = 0; nt < 8; nt++)
            #pragma unroll
            for (int r = 0; r < 4; r++) sacc[nt][r] = 0.f;

        #pragma unroll
        for (int ks = 0; ks < 8; ks++) {
            int k0 = ks*16;
            #pragma unroll
            for (int ntp = 0; ntp < 4; ntp++) {
                int nrow = ntp*16 + (lm >> 1)*8 + lr;
                int col  = k0 + (lm & 1)*8;
                unsigned b0, b1, b2, b3;
                ldsm4(b0, b1, b2, b3, &Ks[nrow*KSTR + col]);
                mma_f16(sacc[ntp*2],   qf[ks][0], qf[ks][1], qf[ks][2], qf[ks][3], b0, b1);
                mma_f16(sacc[ntp*2+1], qf[ks][0], qf[ks][1], qf[ks][2], qf[ks][3], b2, b3);
            }
        }

        if (kt*64 + 63 > qt*128 + w*16) {
            int qg0 = qt*128 + r0, qg1 = qg0 + 8;
            #pragma unroll
            for (int nt = 0; nt < 8; nt++) {
                int c = kt*64 + nt*8 + 2*(lane & 3);
                if (c     > qg0) sacc[nt][0] = -1e30f;
                if (c + 1 > qg0) sacc[nt][1] = -1e30f;
                if (c     > qg1) sacc[nt][2] = -1e30f;
                if (c + 1 > qg1) sacc[nt][3] = -1e30f;
            }
        }

        float mx0 = -1e30f, mx1 = -1e30f;
        #pragma unroll
        for (int nt = 0; nt < 8; nt++) {
            mx0 = fmaxf(mx0, fmaxf(sacc[nt][0], sacc[nt][1]));
            mx1 = fmaxf(mx1, fmaxf(sacc[nt][2], sacc[nt][3]));
        }
        mx0 = fmaxf(mx0, __shfl_xor_sync(0xffffffffu, mx0, 1));
        mx0 = fmaxf(mx0, __shfl_xor_sync(0xffffffffu, mx0, 2));
        mx1 = fmaxf(mx1, __shfl_xor_sync(0xffffffffu, mx1, 1));
        mx1 = fmaxf(mx1, __shfl_xor_sync(0xffffffffu, mx1, 2));
        float mn0 = fmaxf(m0, mx0), mn1 = fmaxf(m1, mx1);
        float corr0 = __expf(m0 - mn0), corr1 = __expf(m1 - mn1);
        m0 = mn0; m1 = mn1;

        float sum0 = 0.f, sum1 = 0.f;
        #pragma unroll
        for (int nt = 0; nt < 8; nt++) {
            sacc[nt][0] = __expf(sacc[nt][0] - mn0);
            sacc[nt][1] = __expf(sacc[nt][1] - mn0);
            sacc[nt][2] = __expf(sacc[nt][2] - mn1);
            sacc[nt][3] = __expf(sacc[nt][3] - mn1);
            sum0 += sacc[nt][0] + sacc[nt][1];
            sum1 += sacc[nt][2] + sacc[nt][3];
        }
        sum0 += __shfl_xor_sync(0xffffffffu, sum0, 1);
        sum0 += __shfl_xor_sync(0xffffffffu, sum0, 2);
        sum1 += __shfl_xor_sync(0xffffffffu, sum1, 1);
        sum1 += __shfl_xor_sync(0xffffffffu, sum1, 2);
        l0 = l0*corr0 + sum0;
        l1 = l1*corr1 + sum1;

        #pragma unroll
        for (int nt = 0; nt < 16; nt++) {
            o[nt][0] *= corr0; o[nt][1] *= corr0;
            o[nt][2] *= corr1; o[nt][3] *= corr1;
        }

        #pragma unroll
        for (int kc = 0; kc < 4; kc++) {
            unsigned pa0 = h2u(sacc[2*kc][0],   sacc[2*kc][1]);
            unsigned pa1 = h2u(sacc[2*kc][2],   sacc[2*kc][3]);
            unsigned pa2 = h2u(sacc[2*kc+1][0], sacc[2*kc+1][1]);
            unsigned pa3 = h2u(sacc[2*kc+1][2], sacc[2*kc+1][3]);
            int k0 = kc*16;
            #pragma unroll
            for (int dt = 0; dt < 8; dt++) {
                int vrow = k0 + (lm & 1)*8 + lr;
                int vcol = dt*16 + (lm >> 1)*8;
                unsigned b0, b1, b2, b3;
                ldsm4t(b0, b1, b2, b3, &Vs[vrow*KSTR + vcol]);
                mma_f16(o[2*dt],   pa0, pa1, pa2, pa3, b0, b1);
                mma_f16(o[2*dt+1], pa0, pa1, pa2, pa3, b2, b3);
            }
        }
    }

    float inv0 = 1.0f / (l0 + 1e-5f);
    float inv1 = 1.0f / (l1 + 1e-5f);
    size_t row0 = (size_t)(b*Sn + qt*128 + r0);
    __half* op0 = g_attn_h + row0*HDn + h*Dn;
    __half* op1 = g_attn_h + (row0+8)*HDn + h*Dn;
    #pragma unroll
    for (int nt = 0; nt < 16; nt++) {
        int d = nt*8 + 2*(lane & 3);
        *(unsigned*)&op0[d] = h2u(o[nt][0]*inv0, o[nt][1]*inv0);
        *(unsigned*)&op1[d] = h2u(o[nt][2]*inv1, o[nt][3]*inv1);
    }
}

// ---------------- launch ----------------
extern "C" void kernel_launch(void* const* d_in, const int* in_sizes, int n_in,
                              void* d_out, int out_size) {
    const float* hidden  = (const float*)d_in[0];
    const int*   pos_ids = (const int*)  d_in[1];
    const float* w_q     = (const float*)d_in[2];
    const float* w_kv_a  = (const float*)d_in[3];
    const float* w_kv_b  = (const float*)d_in[4];
    const float* w_o     = (const float*)d_in[5];
    const float* kv_ln_w = (const float*)d_in[6];
    float* out = (float*)d_out;

    __half *phid, *pwq, *pwkva, *pwkvb, *pwo;
    __half *pq, *pkva, *pckv, *pkv, *pattn;
    cudaGetSymbolAddress((void**)&phid,  g_hid_h);
    cudaGetSymbolAddress((void**)&pwq,   g_wq_t);
    cudaGetSymbolAddress((void**)&pwkva, g_wkva_t);
    cudaGetSymbolAddress((void**)&pwkvb, g_wkvb_t);
    cudaGetSymbolAddress((void**)&pwo,   g_wo_t);
    cudaGetSymbolAddress((void**)&pq,    g_q_h);
    cudaGetSymbolAddress((void**)&pkva,  g_kva_h);
    cudaGetSymbolAddress((void**)&pckv,  g_ckv_h);
    cudaGetSymbolAddress((void**)&pkv,   g_kv_h);
    cudaGetSymbolAddress((void**)&pattn, g_attn_h);

    cudaFuncSetAttribute(gemm_f16, cudaFuncAttributeMaxDynamicSharedMemorySize,
                         GEMM_SMEM_BYTES);
    cudaFuncSetAttribute(flash_f16_kernel, cudaFuncAttributeMaxDynamicSharedMemorySize,
                         FLASH_SMEM_BYTES);

    init_invfreq_kernel<<<1, 64>>>();
    round_half_kernel<<<(BSn*HIDn/4 + 255)/256, 256>>>(hidden, phid, BSn*HIDn/4);

    transpose_half_kernel<<<dim3(HDn/32, HIDn/32), 256>>>(w_q, pwq, HIDn, HDn);
    gemm_f16<<<dim3(HDn/128, BSn/128), 128, GEMM_SMEM_BYTES>>>(phid, pwq, pq, BSn, HDn, HIDn, 1);

    transpose_half_kernel<<<dim3(KVAN/32, HIDn/32), 256>>>(w_kv_a, pwkva, HIDn, KVAN);
    gemm_f16<<<dim3(KVAN/128, BSn/128), 128, GEMM_SMEM_BYTES>>>(phid, pwkva, pkva, BSn, KVAN, HIDn, 1);

    norm_ropek_kernel<<<BSn, 128>>>(kv_ln_w, pos_ids);

    transpose_half_kernel<<<dim3((Hn*2*Dn)/32, RANKn/32), 256>>>(w_kv_b, pwkvb, RANKn, Hn*2*Dn);
    gemm_f16<<<dim3((Hn*2*Dn)/128, BSn/128), 128, GEMM_SMEM_BYTES>>>(pckv, pwkvb, pkv, BSn, Hn*2*Dn, RANKn, 1);

    rope_q_kernel<<<(BSn*Hn)/4, 256>>>(pos_ids);

    flash_f16_kernel<<<dim3(Sn/128, Bn*Hn), 256, FLASH_SMEM_BYTES>>>();

    transpose_half_kernel<<<dim3(HIDn/32, HDn/32), 256>>>(w_o, pwo, HDn, HIDn);
    gemm_f16<<<dim3(HIDn/128, BSn/128), 128, GEMM_SMEM_BYTES>>>(pattn, pwo, out, BSn, HIDn, HIDn, 0);
}

// round 17
// speedup vs baseline: 1.1033x; 1.0894x over previous
#include <cuda_runtime.h>
#include <cuda_fp16.h>
#include <cstdint>
#include <math.h>

// ---------------- problem constants ----------------
#define Bn    2
#define Sn    2048
#define HIDn  2048
#define Hn    16
#define Dn    128
#define RANKn 512
#define BSn   (Bn*Sn)        // 4096
#define KVAN  (RANKn+Dn)     // 640
#define HDn   (Hn*Dn)        // 2048

#define MSCALE_F    1.2772588722239781f
#define ATTN_SCALE  0.08838834764831845f

// ---------------- scratch (half everywhere) ----------------
__device__ __half g_hid_h[(size_t)BSn*HIDn];
__device__ __half g_wq_t[(size_t)HDn*HIDn];
__device__ __half g_wkva_t[(size_t)KVAN*HIDn];
__device__ __half g_wkvb_t[(size_t)Hn*2*Dn*RANKn];
__device__ __half g_wo_t[(size_t)HIDn*HDn];
__device__ __half g_q_h[(size_t)BSn*HDn];
__device__ __half g_kva_h[(size_t)BSn*KVAN];
__device__ __half g_ckv_h[(size_t)BSn*RANKn];
__device__ __half g_kv_h[(size_t)BSn*Hn*2*Dn];
__device__ __half g_krope_h[(size_t)BSn*Dn];
__device__ __half g_attn_h[(size_t)BSn*HDn];
__device__ float  g_invfreq[Dn/2];

// ---------------- helpers ----------------
__device__ __forceinline__ unsigned h2u(float a, float b) {
    __half2 h = __floats2half2_rn(a, b);
    return *(unsigned*)&h;
}
__device__ __forceinline__ unsigned hadd2u(unsigned a, unsigned b) {
    __half2 r = __hadd2(*(__half2*)&a, *(__half2*)&b);
    return *(unsigned*)&r;
}

__device__ __forceinline__ void mma_f16(float* c, unsigned a0, unsigned a1, unsigned a2,
                                        unsigned a3, unsigned b0, unsigned b1) {
    asm volatile(
        "mma.sync.aligned.m16n8k16.row.col.f32.f16.f16.f32 "
        "{%0,%1,%2,%3}, {%4,%5,%6,%7}, {%8,%9}, {%0,%1,%2,%3};"
        : "+f"(c[0]), "+f"(c[1]), "+f"(c[2]), "+f"(c[3])
        : "r"(a0), "r"(a1), "r"(a2), "r"(a3), "r"(b0), "r"(b1));
}

__device__ __forceinline__ void ldsm4(unsigned& r0, unsigned& r1, unsigned& r2, unsigned& r3,
                                      const __half* p) {
    unsigned a = (unsigned)__cvta_generic_to_shared(p);
    asm volatile("ldmatrix.sync.aligned.m8n8.x4.shared.b16 {%0,%1,%2,%3}, [%4];"
        : "=r"(r0), "=r"(r1), "=r"(r2), "=r"(r3) : "r"(a));
}
__device__ __forceinline__ void ldsm4t(unsigned& r0, unsigned& r1, unsigned& r2, unsigned& r3,
                                       const __half* p) {
    unsigned a = (unsigned)__cvta_generic_to_shared(p);
    asm volatile("ldmatrix.sync.aligned.m8n8.x4.trans.shared.b16 {%0,%1,%2,%3}, [%4];"
        : "=r"(r0), "=r"(r1), "=r"(r2), "=r"(r3) : "r"(a));
}

__device__ __forceinline__ void cp16(void* smem_dst, const void* gmem_src) {
    unsigned d = (unsigned)__cvta_generic_to_shared(smem_dst);
    asm volatile("cp.async.cg.shared.global [%0], [%1], 16;" :: "r"(d), "l"(gmem_src));
}
__device__ __forceinline__ void cp_commit() { asm volatile("cp.async.commit_group;"); }
__device__ __forceinline__ void cp_wait0()  { asm volatile("cp.async.wait_group 0;"); }
__device__ __forceinline__ void cp_wait1()  { asm volatile("cp.async.wait_group 1;"); }

// ---------------- f32 -> half copy (hidden) ----------------
__global__ __launch_bounds__(256) void round_half_kernel(const float* __restrict__ src,
                                                         __half* __restrict__ dst, int n4) {
    int i = blockIdx.x * 256 + threadIdx.x;
    if (i >= n4) return;
    float4 v = ((const float4*)src)[i];
    uint2 o;
    o.x = h2u(v.x, v.y);
    o.y = h2u(v.z, v.w);
    ((uint2*)dst)[i] = o;
}

// ---------------- transpose + halve weights ----------------
__global__ __launch_bounds__(256) void transpose_half_kernel(const float* __restrict__ src,
                                                             __half* __restrict__ dst,
                                                             int K, int N) {
    __shared__ float tile[32][33];
    int k0 = blockIdx.y * 32, n0 = blockIdx.x * 32;
    int tx = threadIdx.x & 31, ty = threadIdx.x >> 5;
    #pragma unroll
    for (int j = 0; j < 32; j += 8)
        tile[ty + j][tx] = src[(size_t)(k0 + ty + j) * N + n0 + tx];
    __syncthreads();
    #pragma unroll
    for (int j = 0; j < 32; j += 8)
        dst[(size_t)(n0 + ty + j) * K + k0 + tx] = __float2half_rn(tile[tx][ty + j]);
}

// ---------------- YaRN inv_freq ----------------
__global__ void init_invfreq_kernel() {
    int i = threadIdx.x;
    if (i >= Dn/2) return;
    const double base = 500000.0;
    const double two_pi = 6.283185307179586;
    double pf = exp(((double)(2*i) / (double)Dn) * log(base));
    double extrap = 1.0 / pf;
    double interp = 1.0 / (16.0 * pf);
    double lowf  = floor((double)Dn * log(8192.0 / (32.0 * two_pi)) / (2.0 * log(base)));
    double highf = ceil ((double)Dn * log(8192.0 / ( 1.0 * two_pi)) / (2.0 * log(base)));
    if (lowf < 0.0) lowf = 0.0;
    if (highf > (double)(Dn-1)) highf = (double)(Dn-1);
    double denom = highf - lowf;
    if (denom < 1.0) denom = 1.0;
    double sm = ((double)i - lowf) / denom;
    sm = fmin(fmax(sm, 0.0), 1.0);
    g_invfreq[i] = (float)((1.0 - sm) * interp + sm * extrap);
}

// ---------------- fp16 GEMM (4 warps, 64x64 warp tile, 3-stage) ----------------
#define GSTR 72
#define NSTG 3
#define G_STAGE (128*GSTR)
#define GEMM_SMEM_BYTES (2*NSTG*G_STAGE*2)

__global__ __launch_bounds__(128, 2) void gemm_f16(const __half* __restrict__ A,
                                                   const __half* __restrict__ Bt,
                                                   void* __restrict__ Cv,
                                                   int M, int N, int K, int outHalf) {
    extern __shared__ __half smh[];

    int tid = threadIdx.x;
    int lane = tid & 31, warp = tid >> 5;
    int wm = warp >> 1, wn = warp & 1;
    int bx = blockIdx.x, by = blockIdx.y;

    const int ar  = tid >> 3;
    const int ac8 = (tid & 7) << 3;

    const __half* Abase = A  + (size_t)(by*128)*K;
    const __half* Bbase = Bt + (size_t)(bx*128)*K;

    float acc[4][8][4];
    #pragma unroll
    for (int i = 0; i < 4; i++)
        #pragma unroll
        for (int j = 0; j < 8; j++)
            #pragma unroll
            for (int r = 0; r < 4; r++) acc[i][j][r] = 0.f;

    int T = K >> 6;

    auto issue_tile = [&](int t) {
        int s = t % NSTG;
        __half* Ad = smh + s*G_STAGE;
        __half* Bd = smh + (NSTG + s)*G_STAGE;
        int kt = t << 6;
        #pragma unroll
        for (int l = 0; l < 8; l++) {
            int row = ar + l*16;
            cp16(&Ad[row*GSTR + ac8], &Abase[(size_t)row*K + kt + ac8]);
            cp16(&Bd[row*GSTR + ac8], &Bbase[(size_t)row*K + kt + ac8]);
        }
    };

    issue_tile(0);
    cp_commit();
    if (T > 1) issue_tile(1);
    cp_commit();

    const int lm = lane >> 3;
    const int lr = lane & 7;

    for (int t = 0; t < T; t++) {
        cp_wait1();
        __syncthreads();

        if (t + 2 < T) issue_tile(t + 2);
        cp_commit();

        const __half* As_ = smh + (t % NSTG)*G_STAGE;
        const __half* Bs_ = smh + (NSTG + t % NSTG)*G_STAGE;

        #pragma unroll
        for (int ks = 0; ks < 4; ks++) {
            int k0 = ks*16;
            unsigned af[4][4];
            #pragma unroll
            for (int mt = 0; mt < 4; mt++) {
                int row = wm*64 + mt*16 + (lm & 1)*8 + lr;
                int col = k0 + (lm >> 1)*8;
                ldsm4(af[mt][0], af[mt][1], af[mt][2], af[mt][3], &As_[row*GSTR + col]);
            }
            #pragma unroll
            for (int ntp = 0; ntp < 4; ntp++) {
                int nrow = wn*64 + ntp*16 + (lm >> 1)*8 + lr;
                int col  = k0 + (lm & 1)*8;
                unsigned b0, b1, b2, b3;
                ldsm4(b0, b1, b2, b3, &Bs_[nrow*GSTR + col]);
                #pragma unroll
                for (int mt = 0; mt < 4; mt++) {
                    mma_f16(acc[mt][ntp*2],   af[mt][0], af[mt][1], af[mt][2], af[mt][3], b0, b1);
                    mma_f16(acc[mt][ntp*2+1], af[mt][0], af[mt][1], af[mt][2], af[mt][3], b2, b3);
                }
            }
        }
    }

    if (outHalf) {
        __half* C = (__half*)Cv;
        #pragma unroll
        for (int mt = 0; mt < 4; mt++) {
            int row = by*128 + wm*64 + mt*16 + (lane >> 2);
            #pragma unroll
            for (int nt = 0; nt < 8; nt++) {
                int col = bx*128 + wn*64 + nt*8 + 2*(lane & 3);
                *(unsigned*)&C[(size_t)row*N + col]     = h2u(acc[mt][nt][0], acc[mt][nt][1]);
                *(unsigned*)&C[(size_t)(row+8)*N + col] = h2u(acc[mt][nt][2], acc[mt][nt][3]);
            }
        }
    } else {
        float* C = (float*)Cv;
        #pragma unroll
        for (int mt = 0; mt < 4; mt++) {
            int row = by*128 + wm*64 + mt*16 + (lane >> 2);
            #pragma unroll
            for (int nt = 0; nt < 8; nt++) {
                int col = bx*128 + wn*64 + nt*8 + 2*(lane & 3);
                *(float2*)&C[(size_t)row*N + col]     = make_float2(acc[mt][nt][0], acc[mt][nt][1]);
                *(float2*)&C[(size_t)(row+8)*N + col] = make_float2(acc[mt][nt][2], acc[mt][nt][3]);
            }
        }
    }
}

// ---------------- fused RMSNorm + RoPE-k ----------------
__global__ __launch_bounds__(128) void norm_ropek_kernel(const float* __restrict__ w,
                                                         const int* __restrict__ pos_ids) {
    int row = blockIdx.x;
    const __half* x = g_kva_h + (size_t)row * KVAN;
    __half* y = g_ckv_h + (size_t)row * RANKn;
    int tid = threadIdx.x;
    uint2 u = *(const uint2*)&x[tid*4];
    __half2 h0 = *(__half2*)&u.x, h1 = *(__half2*)&u.y;
    float f0 = __low2float(h0), f1 = __high2float(h0);
    float f2 = __low2float(h1), f3 = __high2float(h1);
    float ss = f0*f0 + f1*f1 + f2*f2 + f3*f3;
    #pragma unroll
    for (int off = 16; off >= 1; off >>= 1)
        ss += __shfl_xor_sync(0xffffffffu, ss, off);
    __shared__ float warp_s[4];
    if ((tid & 31) == 0) warp_s[tid >> 5] = ss;
    __syncthreads();
    float total = warp_s[0] + warp_s[1] + warp_s[2] + warp_s[3];
    float inv = rsqrtf(total * (1.0f/(float)RANKn) + 1e-6f);
    float4 wv = *(const float4*)&w[tid*4];
    uint2 o;
    o.x = h2u(f0*wv.x*inv, f1*wv.y*inv);
    o.y = h2u(f2*wv.z*inv, f3*wv.w*inv);
    *(uint2*)&y[tid*4] = o;

    if (tid < 64) {
        float p = (float)pos_ids[row];
        float f = p * g_invfreq[tid];
        float sv, cv;
        sincosf(f, &sv, &cv);
        cv *= MSCALE_F; sv *= MSCALE_F;
        const __half* kr = x + RANKn;
        float x0 = __half2float(kr[tid]), x1 = __half2float(kr[tid+64]);
        __half* ok = g_krope_h + (size_t)row * Dn;
        ok[tid]    = __float2half_rn(x0*cv - x1*sv);
        ok[tid+64] = __float2half_rn(x1*cv + x0*sv);
    }
}

// ---------------- RoPE q ----------------
__global__ __launch_bounds__(256) void rope_q_kernel(const int* __restrict__ pos_ids) {
    int t = blockIdx.x * 4 + (threadIdx.x >> 6);
    int d = threadIdx.x & 63;
    int bs = t >> 4;
    float p = (float)pos_ids[bs];
    float f = p * g_invfreq[d];
    float sv, cv;
    sincosf(f, &sv, &cv);
    cv *= MSCALE_F; sv *= MSCALE_F;
    __half* q = g_q_h + (size_t)t * Dn;
    float x0 = __half2float(q[d]), x1 = __half2float(q[d+64]);
    q[d]    = __float2half_rn((x0*cv - x1*sv) * ATTN_SCALE);
    q[d+64] = __float2half_rn((x1*cv + x0*sv) * ATTN_SCALE);
}

// ---------------- fp16 flash attention ----------------
#define KSTR 136
#define FSTG (64*KSTR)
#define FLASH_SMEM_BYTES (4*FSTG*2)

__global__ __launch_bounds__(256) void flash_f16_kernel() {
    extern __shared__ __half smh[];

    int tid = threadIdx.x;
    int lane = tid & 31, w = tid >> 5;
    int qt = gridDim.x - 1 - blockIdx.x;
    int bh = blockIdx.y;
    int b = bh >> 4, h = bh & 15;

    const int lm = lane >> 3, lr = lane & 7;
    const int r0 = w*16 + (lane >> 2);

    __half* Qs = smh + 2*FSTG;
    const __half* qbase = g_q_h + ((size_t)(b*Sn + qt*128)) * HDn + h*Dn;
    #pragma unroll
    for (int t8 = 0; t8 < 8; t8++) {
        int i = tid + t8*256;
        int r = i >> 4, d8 = (i & 15) << 3;
        *(uint4*)&Qs[r*KSTR + d8] = *(const uint4*)&qbase[(size_t)r*HDn + d8];
    }
    __syncthreads();
    unsigned qf[8][4];
    #pragma unroll
    for (int ks = 0; ks < 8; ks++) {
        int row = w*16 + (lm & 1)*8 + lr;
        int col = ks*16 + (lm >> 1)*8;
        ldsm4(qf[ks][0], qf[ks][1], qf[ks][2], qf[ks][3], &Qs[row*KSTR + col]);
    }
    __syncthreads();

    float o[16][4];
    float m0 = -1e30f, m1 = -1e30f, l0 = 0.f, l1 = 0.f;
    #pragma unroll
    for (int nt = 0; nt < 16; nt++)
        #pragma unroll
        for (int r = 0; r < 4; r++) o[nt][r] = 0.f;

    const int nkt = 2*qt + 2;
    uint4 kn[4], kr4[4];

    {
        size_t tok0 = (size_t)(b*Sn);
        __half* Vs = smh + FSTG;
        #pragma unroll
        for (int c = 0; c < 4; c++) {
            int i = tid + c*256;
            int r = i >> 4, d8 = (i & 15) << 3;
            size_t base = (tok0 + r)*((size_t)Hn*2*Dn) + h*256;
            kn[c]  = *(const uint4*)&g_kv_h[base + d8];
            kr4[c] = *(const uint4*)&g_krope_h[(tok0 + r)*Dn + d8];
            cp16(&Vs[r*KSTR + d8], &g_kv_h[base + 128 + d8]);
        }
        cp_commit();
    }

    for (int kt = 0; kt < nkt; kt++) {
        int st = kt & 1;
        __half* Ks = smh + st*2*FSTG;
        __half* Vs = Ks + FSTG;

        #pragma unroll
        for (int c = 0; c < 4; c++) {
            int i = tid + c*256;
            int r = i >> 4, d8 = (i & 15) << 3;
            uint4 ko;
            ko.x = hadd2u(kn[c].x, kr4[c].x);
            ko.y = hadd2u(kn[c].y, kr4[c].y);
            ko.z = hadd2u(kn[c].z, kr4[c].z);
            ko.w = hadd2u(kn[c].w, kr4[c].w);
            *(uint4*)&Ks[r*KSTR + d8] = ko;
        }
        cp_wait0();
        __syncthreads();

        if (kt + 1 < nkt) {
            size_t tok1 = (size_t)(b*Sn + (kt+1)*64);
            __half* Vn = smh + (st ^ 1)*2*FSTG + FSTG;
            #pragma unroll
            for (int c = 0; c < 4; c++) {
                int i = tid + c*256;
                int r = i >> 4, d8 = (i & 15) << 3;
                size_t base = (tok1 + r)*((size_t)Hn*2*Dn) + h*256;
                kn[c]  = *(const uint4*)&g_kv_h[base + d8];
                kr4[c] = *(const uint4*)&g_krope_h[(tok1 + r)*Dn + d8];
                cp16(&Vn[r*KSTR + d8], &g_kv_h[base + 128 + d8]);
            }
            cp_commit();
        }

        float sacc[8][4];
        #pragma unroll
        for (int nt = 0; nt < 8; nt++)
            #pragma unroll
            for (int r = 0; r < 4; r++) sacc[nt][r] = 0.f;

        #pragma unroll
        for (int ks = 0; ks < 8; ks++) {
            int k0 = ks*16;
            #pragma unroll
            for (int ntp = 0; ntp < 4; ntp++) {
                int nrow = ntp*16 + (lm >> 1)*8 + lr;
                int col  = k0 + (lm & 1)*8;
                unsigned b0, b1, b2, b3;
                ldsm4(b0, b1, b2, b3, &Ks[nrow*KSTR + col]);
                mma_f16(sacc[ntp*2],   qf[ks][0], qf[ks][1], qf[ks][2], qf[ks][3], b0, b1);
                mma_f16(sacc[ntp*2+1], qf[ks][0], qf[ks][1], qf[ks][2], qf[ks][3], b2, b3);
            }
        }

        if (kt*64 + 63 > qt*128 + w*16) {
            int qg0 = qt*128 + r0, qg1 = qg0 + 8;
            #pragma unroll
            for (int nt = 0; nt < 8; nt++) {
                int c = kt*64 + nt*8 + 2*(lane & 3);
                if (c     > qg0) sacc[nt][0] = -1e30f;
                if (c + 1 > qg0) sacc[nt][1] = -1e30f;
                if (c     > qg1) sacc[nt][2] = -1e30f;
                if (c + 1 > qg1) sacc[nt][3] = -1e30f;
            }
        }

        float mx0 = -1e30f, mx1 = -1e30f;
        #pragma unroll
        for (int nt = 0; nt < 8; nt++) {
            mx0 = fmaxf(mx0, fmaxf(sacc[nt][0], sacc[nt][1]));
            mx1 = fmaxf(mx1, fmaxf(sacc[nt][2], sacc[nt][3]));
        }
        mx0 = fmaxf(mx0, __shfl_xor_sync(0xffffffffu, mx0, 1));
        mx0 = fmaxf(mx0, __shfl_xor_sync(0xffffffffu, mx0, 2));
        mx1 = fmaxf(mx1, __shfl_xor_sync(0xffffffffu, mx1, 1));
        mx1 = fmaxf(mx1, __shfl_xor_sync(0xffffffffu, mx1, 2));
        float mn0 = fmaxf(m0, mx0), mn1 = fmaxf(m1, mx1);
        float corr0 = __expf(m0 - mn0), corr1 = __expf(m1 - mn1);
        m0 = mn0; m1 = mn1;

        float sum0 = 0.f, sum1 = 0.f;
        #pragma unroll
        for (int nt = 0; nt < 8; nt++) {
            sacc[nt][0] = __expf(sacc[nt][0] - mn0);
            sacc[nt][1] = __expf(sacc[nt][1] - mn0);
            sacc[nt][2] = __expf(sacc[nt][2] - mn1);
            sacc[nt][3] = __expf(sacc[nt][3] - mn1);
            sum0 += sacc[nt][0] + sacc[nt][1];
            sum1 += sacc[nt][2] + sacc[nt][3];
        }
        sum0 += __shfl_xor_sync(0xffffffffu, sum0, 1);
        sum0 += __shfl_xor_sync(0xffffffffu, sum0, 2);
        sum1 += __shfl_xor_sync(0xffffffffu, sum1, 1);
        sum1 += __shfl_xor_sync(0xffffffffu, sum1, 2);
        l0 = l0*corr0 + sum0;
        l1 = l1*corr1 + sum1;

        #pragma unroll
        for (int nt = 0; nt < 16; nt++) {
            o[nt][0] *= corr0; o[nt][1] *= corr0;
            o[nt][2] *= corr1; o[nt][3] *= corr1;
        }

        #pragma unroll
        for (int kc = 0; kc < 4; kc++) {
            unsigned pa0 = h2u(sacc[2*kc][0],   sacc[2*kc][1]);
            unsigned pa1 = h2u(sacc[2*kc][2],   sacc[2*kc][3]);
            unsigned pa2 = h2u(sacc[2*kc+1][0], sacc[2*kc+1][1]);
            unsigned pa3 = h2u(sacc[2*kc+1][2], sacc[2*kc+1][3]);
            int k0 = kc*16;
            #pragma unroll
            for (int dt = 0; dt < 8; dt++) {
                int vrow = k0 + (lm & 1)*8 + lr;
                int vcol = dt*16 + (lm >> 1)*8;
                unsigned b0, b1, b2, b3;
                ldsm4t(b0, b1, b2, b3, &Vs[vrow*KSTR + vcol]);
                mma_f16(o[2*dt],   pa0, pa1, pa2, pa3, b0, b1);
                mma_f16(o[2*dt+1], pa0, pa1, pa2, pa3, b2, b3);
            }
        }
    }

    float inv0 = 1.0f / (l0 + 1e-5f);
    float inv1 = 1.0f / (l1 + 1e-5f);
    size_t row0 = (size_t)(b*Sn + qt*128 + r0);
    __half* op0 = g_attn_h + row0*HDn + h*Dn;
    __half* op1 = g_attn_h + (row0+8)*HDn + h*Dn;
    #pragma unroll
    for (int nt = 0; nt < 16; nt++) {
        int d = nt*8 + 2*(lane & 3);
        *(unsigned*)&op0[d] = h2u(o[nt][0]*inv0, o[nt][1]*inv0);
        *(unsigned*)&op1[d] = h2u(o[nt][2]*inv1, o[nt][3]*inv1);
    }
}

// ---------------- launch: fork/join stream concurrency ----------------
extern "C" void kernel_launch(void* const* d_in, const int* in_sizes, int n_in,
                              void* d_out, int out_size) {
    const float* hidden  = (const float*)d_in[0];
    const int*   pos_ids = (const int*)  d_in[1];
    const float* w_q     = (const float*)d_in[2];
    const float* w_kv_a  = (const float*)d_in[3];
    const float* w_kv_b  = (const float*)d_in[4];
    const float* w_o     = (const float*)d_in[5];
    const float* kv_ln_w = (const float*)d_in[6];
    float* out = (float*)d_out;

    __half *phid, *pwq, *pwkva, *pwkvb, *pwo;
    __half *pq, *pkva, *pckv, *pkv, *pattn;
    cudaGetSymbolAddress((void**)&phid,  g_hid_h);
    cudaGetSymbolAddress((void**)&pwq,   g_wq_t);
    cudaGetSymbolAddress((void**)&pwkva, g_wkva_t);
    cudaGetSymbolAddress((void**)&pwkvb, g_wkvb_t);
    cudaGetSymbolAddress((void**)&pwo,   g_wo_t);
    cudaGetSymbolAddress((void**)&pq,    g_q_h);
    cudaGetSymbolAddress((void**)&pkva,  g_kva_h);
    cudaGetSymbolAddress((void**)&pckv,  g_ckv_h);
    cudaGetSymbolAddress((void**)&pkv,   g_kv_h);
    cudaGetSymbolAddress((void**)&pattn, g_attn_h);

    cudaFuncSetAttribute(gemm_f16, cudaFuncAttributeMaxDynamicSharedMemorySize,
                         GEMM_SMEM_BYTES);
    cudaFuncSetAttribute(flash_f16_kernel, cudaFuncAttributeMaxDynamicSharedMemorySize,
                         FLASH_SMEM_BYTES);

    cudaStream_t sA, sB;
    cudaStreamCreateWithFlags(&sA, cudaStreamNonBlocking);
    cudaStreamCreateWithFlags(&sB, cudaStreamNonBlocking);
    cudaEvent_t eFork, eHid, eA, eB, eB2;
    cudaEventCreateWithFlags(&eFork, cudaEventDisableTiming);
    cudaEventCreateWithFlags(&eHid,  cudaEventDisableTiming);
    cudaEventCreateWithFlags(&eA,    cudaEventDisableTiming);
    cudaEventCreateWithFlags(&eB,    cudaEventDisableTiming);
    cudaEventCreateWithFlags(&eB2,   cudaEventDisableTiming);

    // origin stream: invfreq, hidden round; fork after invfreq
    init_invfreq_kernel<<<1, 64>>>();
    cudaEventRecord(eFork, 0);
    round_half_kernel<<<(BSn*HIDn/4 + 255)/256, 256>>>(hidden, phid, BSn*HIDn/4);
    cudaEventRecord(eHid, 0);

    // stream A: q chain (transpose wq || round_half, then q-GEMM, rope_q)
    cudaStreamWaitEvent(sA, eFork, 0);
    transpose_half_kernel<<<dim3(HDn/32, HIDn/32), 256, 0, sA>>>(w_q, pwq, HIDn, HDn);
    cudaStreamWaitEvent(sA, eHid, 0);
    gemm_f16<<<dim3(HDn/128, BSn/128), 128, GEMM_SMEM_BYTES, sA>>>(phid, pwq, pq, BSn, HDn, HIDn, 1);
    rope_q_kernel<<<(BSn*Hn)/4, 256, 0, sA>>>(pos_ids);
    cudaEventRecord(eA, sA);

    // stream B: kv chain (transposes || round_half, then kva-GEMM, norm+ropek, kvb-GEMM)
    cudaStreamWaitEvent(sB, eFork, 0);
    transpose_half_kernel<<<dim3(KVAN/32, HIDn/32), 256, 0, sB>>>(w_kv_a, pwkva, HIDn, KVAN);
    transpose_half_kernel<<<dim3((Hn*2*Dn)/32, RANKn/32), 256, 0, sB>>>(w_kv_b, pwkvb, RANKn, Hn*2*Dn);
    cudaStreamWaitEvent(sB, eHid, 0);
    gemm_f16<<<dim3(KVAN/128, BSn/128), 128, GEMM_SMEM_BYTES, sB>>>(phid, pwkva, pkva, BSn, KVAN, HIDn, 1);
    norm_ropek_kernel<<<BSn, 128, 0, sB>>>(kv_ln_w, pos_ids);
    gemm_f16<<<dim3((Hn*2*Dn)/128, BSn/128), 128, GEMM_SMEM_BYTES, sB>>>(pckv, pwkvb, pkv, BSn, Hn*2*Dn, RANKn, 1);
    cudaEventRecord(eB, sB);
    // w_o transpose overlaps flash
    transpose_half_kernel<<<dim3(HIDn/32, HDn/32), 256, 0, sB>>>(w_o, pwo, HDn, HIDn);
    cudaEventRecord(eB2, sB);

    // join: flash needs q chain + kv chain; o-proj needs flash + w_o transpose
    cudaStreamWaitEvent(0, eA, 0);
    cudaStreamWaitEvent(0, eB, 0);
    flash_f16_kernel<<<dim3(Sn/128, Bn*Hn), 256, FLASH_SMEM_BYTES>>>();
    cudaStreamWaitEvent(0, eB2, 0);
    gemm_f16<<<dim3(HIDn/128, BSn/128), 128, GEMM_SMEM_BYTES>>>(pattn, pwo, out, BSn, HIDn, HIDn, 0);

    cudaEventDestroy(eFork); cudaEventDestroy(eHid);
    cudaEventDestroy(eA); cudaEventDestroy(eB); cudaEventDestroy(eB2);
    cudaStreamDestroy(sA); cudaStreamDestroy(sB);
}